// round 17
// baseline (speedup 1.0000x reference)
#include <cuda_runtime.h>
#include <cuda_fp16.h>
#include <cstdint>

#define EPS 1e-5f

__device__ __half g_Wh[384 * 256];
__device__ float g_bnsc[384];
__device__ float g_bnsh[384];

// ---- branch C (mblk 1,2: c-only, K32, 4-stage, convert-ahead, chained) ----
#define C_A   0u        // A fp16: 4 bufs x 128 rows x 64B (swzA32) = 32 KB
#define C_B   32768u    // B fp16 c: 2 bufs x 32 rows x 256B (swzB) = 16 KB
#define C_S   49152u    // staging fp32 c: 4 bufs x 16 KB           = 64 KB
// ---- branch M (mblk 0: x+c, K32, 2-stage, chained) ----
#define M_A   0u        // 2 x 8 KB
#define M_BX  16384u    // 2 x 8 KB
#define M_BC  32768u    // 2 x 8 KB
#define M_SX  49152u    // 2 x 16 KB
#define M_SC  81920u    // 2 x 16 KB
#define SMEM_TOTAL 114688   // 112 KB -> 2 CTAs/SM

__device__ __forceinline__ uint32_t swzA32(uint32_t o) { return o ^ ((o >> 3) & 0x30); }
__device__ __forceinline__ uint32_t swzB(uint32_t o)   { return o ^ ((o >> 4) & 0x70); }

__device__ __forceinline__ uint32_t s2u(const void* p) {
    uint32_t a;
    asm("{ .reg .u64 t; cvta.to.shared.u64 t, %1; cvt.u32.u64 %0, t; }" : "=r"(a) : "l"(p));
    return a;
}
__device__ __forceinline__ void ldsm_x4(uint32_t* r, uint32_t a) {
    asm volatile("ldmatrix.sync.aligned.m8n8.x4.shared.b16 {%0,%1,%2,%3}, [%4];"
                 : "=r"(r[0]), "=r"(r[1]), "=r"(r[2]), "=r"(r[3]) : "r"(a));
}
__device__ __forceinline__ void ldsm_x4t(uint32_t* r, uint32_t a) {
    asm volatile("ldmatrix.sync.aligned.m8n8.x4.trans.shared.b16 {%0,%1,%2,%3}, [%4];"
                 : "=r"(r[0]), "=r"(r[1]), "=r"(r[2]), "=r"(r[3]) : "r"(a));
}
__device__ __forceinline__ void mma16816(float* d, const uint32_t* a, const uint32_t* b) {
    asm volatile("mma.sync.aligned.m16n8k16.row.col.f32.f16.f16.f32 "
                 "{%0,%1,%2,%3}, {%4,%5,%6,%7}, {%8,%9}, {%0,%1,%2,%3};"
                 : "+f"(d[0]), "+f"(d[1]), "+f"(d[2]), "+f"(d[3])
                 : "r"(a[0]), "r"(a[1]), "r"(a[2]), "r"(a[3]), "r"(b[0]), "r"(b[1]));
}
__device__ __forceinline__ void cpa16(uint32_t dst, const void* src) {
    asm volatile("cp.async.cg.shared.global [%0], [%1], 16;" :: "r"(dst), "l"(src));
}
__device__ __forceinline__ void cpa_commit() { asm volatile("cp.async.commit_group;"); }

// ---------------- prep: W fp32 -> fp16, fold BN ----------------
__global__ void prep_kernel(const float* __restrict__ Wq, const float* __restrict__ Wv,
                            const float* __restrict__ Wk,
                            const float* __restrict__ qg, const float* __restrict__ qb,
                            const float* __restrict__ qm, const float* __restrict__ qv,
                            const float* __restrict__ vg, const float* __restrict__ vb,
                            const float* __restrict__ vm, const float* __restrict__ vv)
{
    int idx = blockIdx.x * blockDim.x + threadIdx.x;
    int stride = gridDim.x * blockDim.x;
    for (int i = idx; i < 384 * 256; i += stride) {
        int r = i >> 8, k = i & 255;
        float w = (r < 64) ? Wq[(r << 8) | k]
                : (r < 320) ? Wv[((r - 64) << 8) | k]
                            : Wk[((r - 320) << 8) | k];
        g_Wh[i] = __float2half_rn(w);
    }
    if (idx < 384) {
        float sc = 1.f, sh = 0.f;
        if (idx < 320) {
            float g, b, m, v;
            if (idx < 64) { g = qg[idx]; b = qb[idx]; m = qm[idx]; v = qv[idx]; }
            else { g = vg[idx-64]; b = vb[idx-64]; m = vm[idx-64]; v = vv[idx-64]; }
            sc = g * rsqrtf(v + EPS);
            sh = b - m * sc;
        }
        g_bnsc[idx] = sc; g_bnsh[idx] = sh;
    }
}

// ---------------- shared epilogue (registers + gmem only) ----------------
__device__ __forceinline__ void epilogue_store(
    float d[2][8][4], float* __restrict__ out,
    int b, int pxb, int ch0, int mw, int nw, int lane, bool isK)
{
    const int g = lane >> 2, cc = lane & 3;
    #pragma unroll
    for (int mt = 0; mt < 2; mt++) {
        const int chA = ch0 + (mw << 5) + (mt << 4) + g;
        float* oA = out + ((size_t)b * 384 + chA) * 4096 + pxb + (nw << 6);
        float* oB = oA + (size_t)8 * 4096;
        if (!isK) {
            float s0 = g_bnsc[chA],     h0 = g_bnsh[chA];
            float s1 = g_bnsc[chA + 8], h1 = g_bnsh[chA + 8];
            #pragma unroll
            for (int nt = 0; nt < 8; nt++) {
                int col = (nt << 3) + (cc << 1);
                *(float2*)(oA + col) = make_float2(fmaf(d[mt][nt][0], s0, h0),
                                                   fmaf(d[mt][nt][1], s0, h0));
                *(float2*)(oB + col) = make_float2(fmaf(d[mt][nt][2], s1, h1),
                                                   fmaf(d[mt][nt][3], s1, h1));
            }
        } else {
            float mx0 = -3.4e38f, mx1 = -3.4e38f;
            #pragma unroll
            for (int nt = 0; nt < 8; nt++) {
                mx0 = fmaxf(mx0, fmaxf(d[mt][nt][0], d[mt][nt][1]));
                mx1 = fmaxf(mx1, fmaxf(d[mt][nt][2], d[mt][nt][3]));
            }
            mx0 = fmaxf(mx0, __shfl_xor_sync(0xffffffffu, mx0, 1));
            mx0 = fmaxf(mx0, __shfl_xor_sync(0xffffffffu, mx0, 2));
            mx1 = fmaxf(mx1, __shfl_xor_sync(0xffffffffu, mx1, 1));
            mx1 = fmaxf(mx1, __shfl_xor_sync(0xffffffffu, mx1, 2));
            float s0 = 0.f, s1 = 0.f;
            #pragma unroll
            for (int nt = 0; nt < 8; nt++) {
                d[mt][nt][0] = __expf(d[mt][nt][0] - mx0); s0 += d[mt][nt][0];
                d[mt][nt][1] = __expf(d[mt][nt][1] - mx0); s0 += d[mt][nt][1];
                d[mt][nt][2] = __expf(d[mt][nt][2] - mx1); s1 += d[mt][nt][2];
                d[mt][nt][3] = __expf(d[mt][nt][3] - mx1); s1 += d[mt][nt][3];
            }
            s0 += __shfl_xor_sync(0xffffffffu, s0, 1);
            s0 += __shfl_xor_sync(0xffffffffu, s0, 2);
            s1 += __shfl_xor_sync(0xffffffffu, s1, 1);
            s1 += __shfl_xor_sync(0xffffffffu, s1, 2);
            float i0 = __frcp_rn(s0), i1 = __frcp_rn(s1);
            #pragma unroll
            for (int nt = 0; nt < 8; nt++) {
                int col = (nt << 3) + (cc << 1);
                *(float2*)(oA + col) = make_float2(d[mt][nt][0] * i0, d[mt][nt][1] * i0);
                *(float2*)(oB + col) = make_float2(d[mt][nt][2] * i1, d[mt][nt][3] * i1);
            }
        }
    }
}

// ---------------- main kernel (2 chained pixel tiles per CTA) ----------------
__global__ __launch_bounds__(256, 2)
void main_kernel(const float* __restrict__ x, const float* __restrict__ c,
                 float* __restrict__ out)
{
    extern __shared__ char smem[];
    const uint32_t sb = s2u(smem);
    const int tid = threadIdx.x, wid = tid >> 5, lane = tid & 31;
    const int mw = wid >> 1, nw = wid & 1;           // warp grid 4(M) x 2(N)
    const int bid = blockIdx.x;
    const int mblk = bid % 3;
    const int u = bid / 3;                           // 0..511 pair-tiles
    const int b = u >> 4;                            // tile0 = 2u -> b = 2u>>5
    const int pxb0 = ((u << 1) & 31) << 7;           // tile g>>3 at pxb0 + 128*(g>>3)
    const int ch0 = mblk << 7;

    float d[2][8][4];
    #pragma unroll
    for (int mt = 0; mt < 2; mt++)
        #pragma unroll
        for (int nt = 0; nt < 8; nt++)
            d[mt][nt][0] = d[mt][nt][1] = d[mt][nt][2] = d[mt][nt][3] = 0.f;

    if (mblk != 0) {
        // ===== branch C: c-only, 16 global chunks over 2 tiles, 4-stage ring =====
        auto issue = [&](int g) {                     // g = global chunk 0..15
            const int kc = (g & 7) << 5;
            const int px = pxb0 + ((g >> 3) << 7);
            const uint32_t asel = C_A + (uint32_t)((g & 3) << 13);
            #pragma unroll
            for (int i = 0; i < 2; i++) {             // A: 512 granules
                int idx = tid + (i << 8);
                int r = idx >> 2, uu = idx & 3;
                cpa16(sb + asel + swzA32((uint32_t)((r << 6) + (uu << 4))),
                      g_Wh + ((ch0 + r) << 8) + kc + (uu << 3));
            }
            const uint32_t ssel = C_S + (uint32_t)((g & 3) << 14);
            #pragma unroll
            for (int i = 0; i < 4; i++) {             // stg c: 1024 granules
                int idx = tid + (i << 8);
                int kk = idx >> 5, p = idx & 31;
                cpa16(sb + ssel + (uint32_t)((kk << 9) + (p << 4)),
                      c + (size_t)((b << 8) + kc + kk) * 4096 + px + (p << 2));
            }
            cpa_commit();
        };
        auto convert = [&](int g) {                   // reads only self-written granules
            const uint32_t ssel = C_S + (uint32_t)((g & 3) << 14);
            const uint32_t bsel = C_B + (uint32_t)((g & 1) << 13);
            #pragma unroll
            for (int i = 0; i < 4; i++) {
                int idx = tid + (i << 8);
                int kk = idx >> 5, p = idx & 31;
                float4 v = *(const float4*)(smem + ssel + (kk << 9) + (p << 4));
                __half2 h0 = __floats2half2_rn(v.x, v.y);
                __half2 h1 = __floats2half2_rn(v.z, v.w);
                *(uint2*)(smem + bsel + swzB((uint32_t)((kk << 8) + (p << 3)))) =
                    make_uint2(*(uint32_t*)&h0, *(uint32_t*)&h1);
            }
        };

        issue(0); issue(1); issue(2);
        asm volatile("cp.async.wait_group 2;");       // chunk 0 landed; 1,2 in flight
        convert(0);

        #pragma unroll
        for (int g = 0; g < 16; g++) {
            __syncthreads();                          // publish A[g], B16[g]
            if (g + 3 < 16) issue(g + 3);             // ring slot (g+3)&3 == (g-1)&3, free
            if (g + 1 < 16) {
                if (g <= 12)      { asm volatile("cp.async.wait_group 2;"); }
                else if (g == 13) { asm volatile("cp.async.wait_group 1;"); }
                else              { asm volatile("cp.async.wait_group 0;"); }
                convert(g + 1);                       // overlaps compute(g)
            }
            const uint32_t abuf = sb + C_A + (uint32_t)((g & 3) << 13);
            const uint32_t bbuf = sb + C_B + (uint32_t)((g & 1) << 13);
            #pragma unroll
            for (int ks = 0; ks < 2; ks++) {
                uint32_t a[2][4], bf[8][2];
                #pragma unroll
                for (int mt = 0; mt < 2; mt++) {
                    int row = (mw << 5) + (mt << 4) + (lane & 15);
                    int kb  = (ks << 5) + ((lane >> 4) << 4);
                    ldsm_x4(a[mt], abuf + swzA32((uint32_t)((row << 6) + kb)));
                }
                #pragma unroll
                for (int p = 0; p < 4; p++) {
                    int krow = (ks << 4) + (lane & 15);
                    int ncol = (nw << 6) + (p << 4) + ((lane >> 4) << 3);
                    uint32_t r[4];
                    ldsm_x4t(r, bbuf + swzB((uint32_t)((krow << 8) + (ncol << 1))));
                    bf[2*p][0] = r[0]; bf[2*p][1] = r[1];
                    bf[2*p+1][0] = r[2]; bf[2*p+1][1] = r[3];
                }
                #pragma unroll
                for (int mt = 0; mt < 2; mt++)
                    #pragma unroll
                    for (int nt = 0; nt < 8; nt++)
                        mma16816(d[mt][nt], a[mt], bf[nt]);
            }
            if (g == 7) {                             // tile-0 epilogue overlaps tile-1 loads
                epilogue_store(d, out, b, pxb0, ch0, mw, nw, lane, (mblk == 2 && mw >= 2));
                #pragma unroll
                for (int mt = 0; mt < 2; mt++)
                    #pragma unroll
                    for (int nt = 0; nt < 8; nt++)
                        d[mt][nt][0] = d[mt][nt][1] = d[mt][nt][2] = d[mt][nt][3] = 0.f;
            }
        }
        epilogue_store(d, out, b, pxb0 + 128, ch0, mw, nw, lane, (mblk == 2 && mw >= 2));
    } else {
        // ===== branch M: x+c, 16 global chunks over 2 tiles, 2-stage =====
        const uint32_t offB = (mw < 2) ? M_BX : M_BC; // q uses x; v uses c
        auto issue = [&](int g) {
            const int kc = (g & 7) << 5;
            const int px = pxb0 + ((g >> 3) << 7);
            const uint32_t sel13 = (uint32_t)((g & 1) << 13);
            const uint32_t sel14 = (uint32_t)((g & 1) << 14);
            #pragma unroll
            for (int i = 0; i < 2; i++) {
                int idx = tid + (i << 8);
                int r = idx >> 2, uu = idx & 3;
                cpa16(sb + M_A + sel13 + swzA32((uint32_t)((r << 6) + (uu << 4))),
                      g_Wh + (r << 8) + kc + (uu << 3));
            }
            #pragma unroll
            for (int i = 0; i < 4; i++) {
                int idx = tid + (i << 8);
                int kk = idx >> 5, p = idx & 31;
                size_t go = (size_t)((b << 8) + kc + kk) * 4096 + px + (p << 2);
                uint32_t so = (uint32_t)((kk << 9) + (p << 4));
                cpa16(sb + M_SC + sel14 + so, c + go);
                cpa16(sb + M_SX + sel14 + so, x + go);
            }
            cpa_commit();
        };
        auto convert_one = [&](uint32_t stg, uint32_t dst16) {
            #pragma unroll
            for (int i = 0; i < 4; i++) {
                int idx = tid + (i << 8);
                int kk = idx >> 5, p = idx & 31;
                float4 v = *(const float4*)(smem + stg + (kk << 9) + (p << 4));
                __half2 h0 = __floats2half2_rn(v.x, v.y);
                __half2 h1 = __floats2half2_rn(v.z, v.w);
                *(uint2*)(smem + dst16 + swzB((uint32_t)((kk << 8) + (p << 3)))) =
                    make_uint2(*(uint32_t*)&h0, *(uint32_t*)&h1);
            }
        };

        issue(0);
        #pragma unroll
        for (int g = 0; g < 16; g++) {
            asm volatile("cp.async.wait_group 0;");
            __syncthreads();
            if (g < 15) issue(g + 1);
            const uint32_t sel13 = (uint32_t)((g & 1) << 13);
            const uint32_t sel14 = (uint32_t)((g & 1) << 14);
            convert_one(M_SC + sel14, M_BC + sel13);
            convert_one(M_SX + sel14, M_BX + sel13);
            __syncthreads();

            const uint32_t abuf = sb + M_A + sel13;
            const uint32_t bbuf = sb + offB + sel13;
            #pragma unroll
            for (int ks = 0; ks < 2; ks++) {
                uint32_t a[2][4], bf[8][2];
                #pragma unroll
                for (int mt = 0; mt < 2; mt++) {
                    int row = (mw << 5) + (mt << 4) + (lane & 15);
                    int kb  = (ks << 5) + ((lane >> 4) << 4);
                    ldsm_x4(a[mt], abuf + swzA32((uint32_t)((row << 6) + kb)));
                }
                #pragma unroll
                for (int p = 0; p < 4; p++) {
                    int krow = (ks << 4) + (lane & 15);
                    int ncol = (nw << 6) + (p << 4) + ((lane >> 4) << 3);
                    uint32_t r[4];
                    ldsm_x4t(r, bbuf + swzB((uint32_t)((krow << 8) + (ncol << 1))));
                    bf[2*p][0] = r[0]; bf[2*p][1] = r[1];
                    bf[2*p+1][0] = r[2]; bf[2*p+1][1] = r[3];
                }
                #pragma unroll
                for (int mt = 0; mt < 2; mt++)
                    #pragma unroll
                    for (int nt = 0; nt < 8; nt++)
                        mma16816(d[mt][nt], a[mt], bf[nt]);
            }
            if (g == 7) {
                epilogue_store(d, out, b, pxb0, 0, mw, nw, lane, false);
                #pragma unroll
                for (int mt = 0; mt < 2; mt++)
                    #pragma unroll
                    for (int nt = 0; nt < 8; nt++)
                        d[mt][nt][0] = d[mt][nt][1] = d[mt][nt][2] = d[mt][nt][3] = 0.f;
            }
        }
        epilogue_store(d, out, b, pxb0 + 128, 0, mw, nw, lane, false);
    }
}

extern "C" void kernel_launch(void* const* d_in, const int* in_sizes, int n_in,
                              void* d_out, int out_size)
{
    const float* x = (const float*)d_in[0];
    const float* c = (const float*)d_in[1];
    prep_kernel<<<96, 256>>>((const float*)d_in[2], (const float*)d_in[3],
                             (const float*)d_in[4], (const float*)d_in[5],
                             (const float*)d_in[6], (const float*)d_in[7],
                             (const float*)d_in[8], (const float*)d_in[9],
                             (const float*)d_in[10], (const float*)d_in[11],
                             (const float*)d_in[12]);
    cudaFuncSetAttribute(main_kernel, cudaFuncAttributeMaxDynamicSharedMemorySize, SMEM_TOTAL);
    main_kernel<<<1536, 256, SMEM_TOTAL>>>(x, c, (float*)d_out);
}